// round 1
// baseline (speedup 1.0000x reference)
#include <cuda_runtime.h>
#include <math.h>

// Shapes: H=24, Mdim=48, C=8, P=8
//   y_rev     (96, 8, 1)
//   M_tilde   (24, 48, 8, 8)
//   M         (24, 48, 24, 48, 8, 8)   ~340 MB  <-- the whole problem
//   sigma(24) lambda_e(24) phi(48,24) phi_tilde(48,24)
// Output u: (8, 1)
//
// u[c] = sum_p M_tilde[0,0,c,p] y[0,p]                                   (term1)
//      + sum_{i,j,p} lam4[i] phi[j,i]      M_tilde[i,j,c,p]   y[j,p]     (term2)
//      + sum_{l,k,p} sig4[l] phi_t[k,l]    M[l,k,0,0,c,p]     y[k,p]     (term3)
//      + sum_{i,j,l,k,p} lam4[i] phi[j,i] sig4[l] phi_t[k,l]
//                                          M[i,j,l,k,c,p]     y[j+k,p]   (term4)

#define HH 24
#define MD 48
#define NBLK (HH*MD)            // 1152
#define TUP  (HH*MD)            // 1152 (l,k) tuples per block
#define S_I  3538944LL          // MD*HH*MD*64
#define S_J  73728LL            // HH*MD*64

__device__ float g_partials[NBLK * 8];

__global__ __launch_bounds__(256) void dsc_main_kernel(
    const float* __restrict__ y_rev,
    const float* __restrict__ M_tilde,
    const float* __restrict__ M,
    const float* __restrict__ sigma,
    const float* __restrict__ lambda_e,
    const float* __restrict__ phi,
    const float* __restrict__ phi_tilde)
{
    __shared__ __align__(16) float wv_sh[TUP * 8];   // 36 KB: weight*y table
    __shared__ __align__(16) float y_sh[96 * 8];     // 3 KB
    __shared__ float sig4_sh[HH];
    __shared__ float red_sh[8 * 8];

    const int tid = threadIdx.x;
    const int bi = blockIdx.x / MD;   // i (and l for term3)
    const int bj = blockIdx.x % MD;   // j (and k for term3)

    // stage y and sigma^(1/4)
    for (int e = tid; e < 96 * 8; e += 256) y_sh[e] = y_rev[e];
    if (tid < HH) sig4_sh[tid] = sqrtf(sqrtf(sigma[tid]));
    __syncthreads();

    const float lam4_i = sqrtf(sqrtf(lambda_e[bi]));
    const float c_ij   = lam4_i * phi[bj * HH + bi];

    // per-block weight*y table: wv[t*8+p] = c_ij * sig4[l] * phi_t[k,l] * y[(j+k),p]
    for (int e = tid; e < TUP * 8; e += 256) {
        int t = e >> 3;
        int p = e & 7;
        int l = t / 48;
        int k = t - l * 48;
        wv_sh[e] = c_ij * sig4_sh[l] * phi_tilde[k * HH + l] * y_sh[(bj + k) * 8 + p];
    }
    __syncthreads();

    const int lane  = tid & 31;
    const int warp  = tid >> 5;
    const int half  = lane >> 4;          // which tuple of the pair
    const int off16 = lane & 15;          // float4 index within tuple
    const int pbase = (off16 & 1) << 2;   // p offset: 0 or 4
    // this lane's output channel c = off16 >> 1

    const float4* __restrict__ Mb =
        reinterpret_cast<const float4*>(M + (size_t)blockIdx.x * S_J);

    float4 acc = make_float4(0.f, 0.f, 0.f, 0.f);

    // 576 tuple-pairs; each warp-iteration streams 2 tuples (512 B)
    #pragma unroll 4
    for (int pp2 = warp; pp2 < TUP / 2; pp2 += 8) {
        int t = pp2 * 2 + half;
        float4 mv = Mb[t * 16 + off16];
        float4 wv = *reinterpret_cast<const float4*>(&wv_sh[t * 8 + pbase]);
        acc.x = fmaf(mv.x, wv.x, acc.x);
        acc.y = fmaf(mv.y, wv.y, acc.y);
        acc.z = fmaf(mv.z, wv.z, acc.z);
        acc.w = fmaf(mv.w, wv.w, acc.w);
    }

    // fold in the small terms: warp0 -> term2 tuple (i,j); warp1 -> term3 tuple (l=i,k=j)
    if (warp < 2 && half == 0) {
        const float* src;
        float w2;
        if (warp == 0) {
            src = M_tilde + (size_t)blockIdx.x * 64;
            w2  = c_ij;
        } else {
            src = M + (size_t)bi * S_I + (size_t)bj * S_J;   // M[l,k,0,0,:,:]
            w2  = sig4_sh[bi] * phi_tilde[bj * HH + bi];
        }
        float4 mv = *reinterpret_cast<const float4*>(src + off16 * 4);
        const float* yb = &y_sh[bj * 8 + pbase];
        acc.x = fmaf(mv.x, w2 * yb[0], acc.x);
        acc.y = fmaf(mv.y, w2 * yb[1], acc.y);
        acc.z = fmaf(mv.z, w2 * yb[2], acc.z);
        acc.w = fmaf(mv.w, w2 * yb[3], acc.w);
    }

    // lane partial for its channel c = off16>>1 (sum of its 4 p's)
    float s = acc.x + acc.y + acc.z + acc.w;
    // combine the 4 lanes sharing a channel: {2c, 2c+1, 2c+16, 2c+17}
    s += __shfl_xor_sync(0xffffffffu, s, 16);
    s += __shfl_xor_sync(0xffffffffu, s, 1);
    if (half == 0 && (off16 & 1) == 0)
        red_sh[warp * 8 + (off16 >> 1)] = s;
    __syncthreads();

    if (tid < 8) {
        float r = 0.f;
        #pragma unroll
        for (int w = 0; w < 8; ++w) r += red_sh[w * 8 + tid];
        g_partials[blockIdx.x * 8 + tid] = r;
    }
}

__global__ __launch_bounds__(256) void dsc_finish_kernel(
    const float* __restrict__ y_rev,
    const float* __restrict__ M_tilde,
    float* __restrict__ out)
{
    // 8 warps, warp w owns output channel w
    const int lane = threadIdx.x & 31;
    const int warp = threadIdx.x >> 5;

    float s = 0.f;
    for (int b = lane; b < NBLK; b += 32)
        s += g_partials[b * 8 + warp];
    #pragma unroll
    for (int d = 16; d > 0; d >>= 1)
        s += __shfl_xor_sync(0xffffffffu, s, d);

    if (lane == 0) {
        float t1 = 0.f;
        #pragma unroll
        for (int p = 0; p < 8; ++p)
            t1 += M_tilde[warp * 8 + p] * y_rev[p];   // M_tilde[0,0,c,p] * y[0,p]
        out[warp] = s + t1;
    }
}

extern "C" void kernel_launch(void* const* d_in, const int* in_sizes, int n_in,
                              void* d_out, int out_size)
{
    const float* y_rev     = (const float*)d_in[0];
    const float* M_tilde   = (const float*)d_in[1];
    const float* M         = (const float*)d_in[2];
    const float* sigma     = (const float*)d_in[3];
    const float* lambda_e  = (const float*)d_in[4];
    const float* phi       = (const float*)d_in[5];
    const float* phi_tilde = (const float*)d_in[6];
    float* out = (float*)d_out;

    dsc_main_kernel<<<NBLK, 256>>>(y_rev, M_tilde, M, sigma, lambda_e, phi, phi_tilde);
    dsc_finish_kernel<<<1, 256>>>(y_rev, M_tilde, out);
}

// round 2
// speedup vs baseline: 1.0856x; 1.0856x over previous
#include <cuda_runtime.h>
#include <math.h>

// Shapes: H=24, Mdim=48, C=8, P=8
// u[c] = sum_p M_tilde[0,0,c,p] y[0,p]                                   (term1)
//      + sum_{i,j,p} lam4[i] phi[j,i]      M_tilde[i,j,c,p]   y[j,p]     (term2)
//      + sum_{l,k,p} sig4[l] phi_t[k,l]    M[l,k,0,0,c,p]     y[k,p]     (term3)
//      + sum_{i,j,l,k,p} lam4[i] phi[j,i] sig4[l] phi_t[k,l]
//                                          M[i,j,l,k,c,p]     y[j+k,p]   (term4)

#define HH 24
#define MD 48
#define NBLK (HH*MD)            // 1152 blocks, one per (i,j)
#define TUP  (HH*MD)            // 1152 (l,k) tuples per block
#define S_I  3538944LL          // MD*HH*MD*64 floats
#define S_J  73728LL            // HH*MD*64 floats

__device__ float        g_partials[NBLK * 8];
__device__ unsigned int g_count = 0;

__global__ __launch_bounds__(256) void dsc_main_kernel(
    const float* __restrict__ y_rev,
    const float* __restrict__ M_tilde,
    const float* __restrict__ M,
    const float* __restrict__ sigma,
    const float* __restrict__ lambda_e,
    const float* __restrict__ phi,
    const float* __restrict__ phi_tilde,
    float* __restrict__ out)
{
    __shared__ __align__(16) float bw_sh[TUP];      // 4.5 KB: c_ij*sig4[l]*phi_t[k,l]
    __shared__ __align__(16) float y_sh[96 * 8];    // 3 KB
    __shared__ float sig4_sh[HH];
    __shared__ float red_sh[8 * 8];
    __shared__ int   last_flag;

    const int tid = threadIdx.x;
    const int bi = blockIdx.x / MD;   // i (and l for term3)
    const int bj = blockIdx.x % MD;   // j (and k for term3)

    for (int e = tid; e < 96 * 8; e += 256) y_sh[e] = y_rev[e];
    if (tid < HH) sig4_sh[tid] = sqrtf(sqrtf(sigma[tid]));
    __syncthreads();

    const float lam4_i = sqrtf(sqrtf(lambda_e[bi]));
    const float c_ij   = lam4_i * phi[bj * HH + bi];

    // per-block scalar weight table (1152 elements)
    for (int e = tid; e < TUP; e += 256) {
        int l = e / 48;
        int k = e - l * 48;
        bw_sh[e] = c_ij * sig4_sh[l] * phi_tilde[k * HH + l];
    }
    __syncthreads();

    const int lane  = tid & 31;
    const int warp  = tid >> 5;
    const int half  = lane >> 4;          // which tuple of the pair
    const int off16 = lane & 15;          // float4 index within tuple
    const int pbase = (off16 & 1) << 2;   // p offset: 0 or 4
    const int ysel  = off16 & 1;          // float4 slot within a y-row

    const float4* __restrict__ Mb =
        reinterpret_cast<const float4*>(M + (size_t)blockIdx.x * S_J);
    const float4* __restrict__ yv4 = reinterpret_cast<const float4*>(y_sh);

    // t = t0 + 16*n; k = t mod 48 has period 3 (t0 < 16), so only 3 y-vectors
    const int t0 = warp * 2 + half;
    const float4 yA = yv4[(bj + t0     ) * 2 + ysel];
    const float4 yB = yv4[(bj + t0 + 16) * 2 + ysel];
    const float4 yC = yv4[(bj + t0 + 32) * 2 + ysel];

    float4 acc = make_float4(0.f, 0.f, 0.f, 0.f);

    #pragma unroll 2
    for (int n = 0; n < 72; n += 3) {
        int t = t0 + n * 16;
        float4 m0 = __ldcs(&Mb[(size_t)(t     ) * 16 + off16]);
        float4 m1 = __ldcs(&Mb[(size_t)(t + 16) * 16 + off16]);
        float4 m2 = __ldcs(&Mb[(size_t)(t + 32) * 16 + off16]);
        float w0 = bw_sh[t];
        float w1 = bw_sh[t + 16];
        float w2 = bw_sh[t + 32];
        acc.x = fmaf(m0.x, w0 * yA.x, acc.x);
        acc.y = fmaf(m0.y, w0 * yA.y, acc.y);
        acc.z = fmaf(m0.z, w0 * yA.z, acc.z);
        acc.w = fmaf(m0.w, w0 * yA.w, acc.w);
        acc.x = fmaf(m1.x, w1 * yB.x, acc.x);
        acc.y = fmaf(m1.y, w1 * yB.y, acc.y);
        acc.z = fmaf(m1.z, w1 * yB.z, acc.z);
        acc.w = fmaf(m1.w, w1 * yB.w, acc.w);
        acc.x = fmaf(m2.x, w2 * yC.x, acc.x);
        acc.y = fmaf(m2.y, w2 * yC.y, acc.y);
        acc.z = fmaf(m2.z, w2 * yC.z, acc.z);
        acc.w = fmaf(m2.w, w2 * yC.w, acc.w);
    }

    // fold the small terms: warp0 -> term2 tuple (i,j); warp1 -> term3 (l=i,k=j)
    if (warp < 2 && half == 0) {
        const float* src;
        float w2;
        if (warp == 0) {
            src = M_tilde + (size_t)blockIdx.x * 64;
            w2  = c_ij;
        } else {
            src = M + (size_t)bi * S_I + (size_t)bj * S_J;   // M[l,k,0,0,:,:]
            w2  = sig4_sh[bi] * phi_tilde[bj * HH + bi];
        }
        float4 mv = *reinterpret_cast<const float4*>(src + off16 * 4);
        const float* yb = &y_sh[bj * 8 + pbase];
        acc.x = fmaf(mv.x, w2 * yb[0], acc.x);
        acc.y = fmaf(mv.y, w2 * yb[1], acc.y);
        acc.z = fmaf(mv.z, w2 * yb[2], acc.z);
        acc.w = fmaf(mv.w, w2 * yb[3], acc.w);
    }

    // lane partial for its channel c = off16>>1
    float s = acc.x + acc.y + acc.z + acc.w;
    s += __shfl_xor_sync(0xffffffffu, s, 16);
    s += __shfl_xor_sync(0xffffffffu, s, 1);
    if (half == 0 && (off16 & 1) == 0)
        red_sh[warp * 8 + (off16 >> 1)] = s;
    __syncthreads();

    if (tid < 8) {
        float r = 0.f;
        #pragma unroll
        for (int w = 0; w < 8; ++w) r += red_sh[w * 8 + tid];
        g_partials[blockIdx.x * 8 + tid] = r;
    }
    __syncthreads();

    // last-block-done final reduction (deterministic: fixed summation order)
    if (tid == 0) {
        __threadfence();
        unsigned int prev = atomicAdd(&g_count, 1u);
        last_flag = (prev == NBLK - 1u);
    }
    __syncthreads();

    if (last_flag) {
        __threadfence();
        // warp w owns output channel w
        float r = 0.f;
        for (int b = lane; b < NBLK; b += 32)
            r += g_partials[b * 8 + warp];
        #pragma unroll
        for (int d = 16; d > 0; d >>= 1)
            r += __shfl_xor_sync(0xffffffffu, r, d);
        if (lane == 0) {
            float t1 = 0.f;
            #pragma unroll
            for (int p = 0; p < 8; ++p)
                t1 += M_tilde[warp * 8 + p] * y_sh[p];   // M_tilde[0,0,c,p]*y[0,p]
            out[warp] = r + t1;
        }
        if (tid == 0) g_count = 0;   // re-arm for next (graph-replayed) launch
    }
}

extern "C" void kernel_launch(void* const* d_in, const int* in_sizes, int n_in,
                              void* d_out, int out_size)
{
    const float* y_rev     = (const float*)d_in[0];
    const float* M_tilde   = (const float*)d_in[1];
    const float* M         = (const float*)d_in[2];
    const float* sigma     = (const float*)d_in[3];
    const float* lambda_e  = (const float*)d_in[4];
    const float* phi       = (const float*)d_in[5];
    const float* phi_tilde = (const float*)d_in[6];
    float* out = (float*)d_out;

    dsc_main_kernel<<<NBLK, 256>>>(y_rev, M_tilde, M, sigma, lambda_e,
                                   phi, phi_tilde, out);
}

// round 3
// speedup vs baseline: 1.3091x; 1.2059x over previous
#include <cuda_runtime.h>
#include <math.h>

// Shapes: H=24, Mdim=48, C=8, P=8
// u[c] = sum_p M_tilde[0,0,c,p] y[0,p]                                   (term1)
//      + sum_{i,j,p} lam4[i] phi[j,i]      M_tilde[i,j,c,p]   y[j,p]     (term2)
//      + sum_{l,k,p} sig4[l] phi_t[k,l]    M[l,k,0,0,c,p]     y[k,p]     (term3)
//      + sum_{i,j,l,k,p} lam4[i] phi[j,i] sig4[l] phi_t[k,l]
//                                          M[i,j,l,k,c,p]     y[j+k,p]   (term4)

#define HH 24
#define MD 48
#define NTILE (HH*MD)               // 1152 (i,j) tiles
#define CHUNKS 8                    // chunks per tile (9 m-steps each)
#define NUNITS (NTILE*CHUNKS)       // 9216 work units
#define GRID 888                    // 148 SMs x 6 CTAs -> single wave
#define S_I  3538944LL              // MD*HH*MD*64 floats
#define S_J  73728LL                // HH*MD*64 floats

__device__ float        g_partials[GRID * 8];
__device__ unsigned int g_count = 0;

__global__ __launch_bounds__(256, 6) void dsc_main_kernel(
    const float* __restrict__ y_rev,
    const float* __restrict__ M_tilde,
    const float* __restrict__ M,
    const float* __restrict__ sigma,
    const float* __restrict__ lambda_e,
    const float* __restrict__ phi,
    const float* __restrict__ phi_tilde,
    float* __restrict__ out)
{
    __shared__ __align__(16) float bw_sh[NTILE];      // 4.5 KB weights, current tile
    __shared__ __align__(16) float y_sh[96 * 8];      // 3 KB
    __shared__ __align__(16) float phit_sh[MD * HH];  // 4.5 KB
    __shared__ float sig4_sh[HH];
    __shared__ float lam4_sh[HH];
    __shared__ float red_sh[8 * 8];
    __shared__ int   last_flag;

    const int tid = threadIdx.x;

    for (int e = tid; e < 96 * 8; e += 256) y_sh[e] = y_rev[e];
    for (int e = tid; e < MD * HH; e += 256) phit_sh[e] = phi_tilde[e];
    if (tid < HH) {
        sig4_sh[tid] = sqrtf(sqrtf(sigma[tid]));
        lam4_sh[tid] = sqrtf(sqrtf(lambda_e[tid]));
    }
    __syncthreads();

    // static balanced unit range for this block
    const int q = NUNITS / GRID;                 // 10
    const int r = NUNITS % GRID;                 // 336
    const int b = blockIdx.x;
    const int ustart = b * q + (b < r ? b : r);
    const int uend   = ustart + q + (b < r ? 1 : 0);

    const int lane  = tid & 31;
    const int warp  = tid >> 5;
    const int half  = lane >> 4;
    const int off16 = lane & 15;
    const int pbase = (off16 & 1) << 2;
    const int ysel  = off16 & 1;
    const int t0    = warp * 2 + half;           // 0..15

    const float4* __restrict__ yv4 = reinterpret_cast<const float4*>(y_sh);

    float4 acc = make_float4(0.f, 0.f, 0.f, 0.f);
    int cur_tile = -1;
    const float4* Mb = nullptr;
    float c_ij = 0.f;
    int ti = 0, tj = 0;
    float4 yA, yB, yC;

    for (int u = ustart; u < uend; ++u) {
        const int tl = u >> 3;
        const int ch = u & 7;

        if (tl != cur_tile) {
            __syncthreads();                      // protect bw_sh rewrite
            ti = tl / MD;
            tj = tl - ti * MD;
            c_ij = lam4_sh[ti] * __ldg(&phi[tj * HH + ti]);
            for (int e = tid; e < NTILE; e += 256) {
                int l = e / 48;
                int k = e - l * 48;
                bw_sh[e] = c_ij * sig4_sh[l] * phit_sh[k * HH + l];
            }
            __syncthreads();
            cur_tile = tl;
            Mb = reinterpret_cast<const float4*>(M + (size_t)tl * S_J);
            yA = yv4[(tj + t0     ) * 2 + ysel];
            yB = yv4[(tj + t0 + 16) * 2 + ysel];
            yC = yv4[(tj + t0 + 32) * 2 + ysel];
        }

        // chunk 0 owner folds the small terms for this tile (once per tile)
        if (ch == 0 && warp < 2 && half == 0) {
            const float* src;
            float w2;
            if (warp == 0) {
                src = M_tilde + (size_t)tl * 64;               // term2 (i,j)
                w2  = c_ij;
            } else {
                src = M + (size_t)ti * S_I + (size_t)tj * S_J; // term3 M[l,k,0,0,:,:]
                w2  = sig4_sh[ti] * phit_sh[tj * HH + ti];
            }
            float4 mv = *reinterpret_cast<const float4*>(src + off16 * 4);
            const float* yb = &y_sh[tj * 8 + pbase];
            acc.x = fmaf(mv.x, w2 * yb[0], acc.x);
            acc.y = fmaf(mv.y, w2 * yb[1], acc.y);
            acc.z = fmaf(mv.z, w2 * yb[2], acc.z);
            acc.w = fmaf(mv.w, w2 * yb[3], acc.w);
        }

        // unit body: 3 triples, t = t0 + 16*m, m in [9*ch, 9*ch+9)
        const int mbase = ch * 9;
        #pragma unroll
        for (int m3 = 0; m3 < 9; m3 += 3) {
            int t = t0 + (mbase + m3) * 16;
            float4 m0 = __ldcs(&Mb[(size_t)(t      ) * 16 + off16]);
            float4 m1 = __ldcs(&Mb[(size_t)(t + 16 ) * 16 + off16]);
            float4 m2 = __ldcs(&Mb[(size_t)(t + 32 ) * 16 + off16]);
            float w0 = bw_sh[t];
            float w1 = bw_sh[t + 16];
            float w2 = bw_sh[t + 32];
            acc.x = fmaf(m0.x, w0 * yA.x, acc.x);
            acc.y = fmaf(m0.y, w0 * yA.y, acc.y);
            acc.z = fmaf(m0.z, w0 * yA.z, acc.z);
            acc.w = fmaf(m0.w, w0 * yA.w, acc.w);
            acc.x = fmaf(m1.x, w1 * yB.x, acc.x);
            acc.y = fmaf(m1.y, w1 * yB.y, acc.y);
            acc.z = fmaf(m1.z, w1 * yB.z, acc.z);
            acc.w = fmaf(m1.w, w1 * yB.w, acc.w);
            acc.x = fmaf(m2.x, w2 * yC.x, acc.x);
            acc.y = fmaf(m2.y, w2 * yC.y, acc.y);
            acc.z = fmaf(m2.z, w2 * yC.z, acc.z);
            acc.w = fmaf(m2.w, w2 * yC.w, acc.w);
        }
    }

    // block reduction: lane partial for channel c = off16>>1
    float s = acc.x + acc.y + acc.z + acc.w;
    s += __shfl_xor_sync(0xffffffffu, s, 16);
    s += __shfl_xor_sync(0xffffffffu, s, 1);
    if (half == 0 && (off16 & 1) == 0)
        red_sh[warp * 8 + (off16 >> 1)] = s;
    __syncthreads();

    if (tid < 8) {
        float rr = 0.f;
        #pragma unroll
        for (int w = 0; w < 8; ++w) rr += red_sh[w * 8 + tid];
        g_partials[blockIdx.x * 8 + tid] = rr;
    }
    __syncthreads();

    // last-block-done final reduction (deterministic fixed order)
    if (tid == 0) {
        __threadfence();
        unsigned int prev = atomicAdd(&g_count, 1u);
        last_flag = (prev == GRID - 1u);
    }
    __syncthreads();

    if (last_flag) {
        __threadfence();
        float rr = 0.f;
        for (int bb = lane; bb < GRID; bb += 32)
            rr += g_partials[bb * 8 + warp];
        #pragma unroll
        for (int d = 16; d > 0; d >>= 1)
            rr += __shfl_xor_sync(0xffffffffu, rr, d);
        if (lane == 0 && warp < 8) {
            float t1 = 0.f;
            #pragma unroll
            for (int p = 0; p < 8; ++p)
                t1 += M_tilde[warp * 8 + p] * y_sh[p];   // term1
            out[warp] = rr + t1;
        }
        if (tid == 0) g_count = 0;   // re-arm for graph replay
    }
}

extern "C" void kernel_launch(void* const* d_in, const int* in_sizes, int n_in,
                              void* d_out, int out_size)
{
    const float* y_rev     = (const float*)d_in[0];
    const float* M_tilde   = (const float*)d_in[1];
    const float* M         = (const float*)d_in[2];
    const float* sigma     = (const float*)d_in[3];
    const float* lambda_e  = (const float*)d_in[4];
    const float* phi       = (const float*)d_in[5];
    const float* phi_tilde = (const float*)d_in[6];
    float* out = (float*)d_out;

    dsc_main_kernel<<<GRID, 256>>>(y_rev, M_tilde, M, sigma, lambda_e,
                                   phi, phi_tilde, out);
}